// round 1
// baseline (speedup 1.0000x reference)
#include <cuda_runtime.h>
#include <cstdint>

// Board: 64x64, 8 channels, channels-last float32. HW = 4096 cells.
// One CTA per batch element. 256 threads x 16 cells/thread.

#define HW_       4096
#define W_        64
#define NTHREADS  256
#define CELLS     16   // HW_ / NTHREADS

__device__ __forceinline__ void merge2min(float& m1, int& i1, float& m2,
                                          float m1b, int i1b, float m2b) {
    // Merge two (smallest, idx-of-smallest-with-row-major-tiebreak, second-smallest)
    if (m1b < m1 || (m1b == m1 && i1b < i1)) {
        m2 = fminf(m1, m2b);
        m1 = m1b; i1 = i1b;
    } else {
        m2 = fminf(m2, m1b);
    }
}

__global__ __launch_bounds__(NTHREADS)
void oracle_kernel(const float* __restrict__ x,
                   const float* __restrict__ opp_start,
                   float* __restrict__ out) {
    const int b   = blockIdx.x;
    const int tid = threadIdx.x;
    const int wid = tid >> 5;
    const int lid = tid & 31;
    const float FINF = __int_as_float(0x7f800000);

    // Each cell = 32 bytes. We load the first float4 (channels 0..3):
    // .y = channel 1 (food), .w = channel 3 (opp).
    const float4* xb = reinterpret_cast<const float4*>(x) + (size_t)b * HW_ * 2;

    // ---------------- Phase 1: load once, build masks + local reductions ----
    float4 v[CELLS];
#pragma unroll
    for (int k = 0; k < CELLS; k++) {
        const int cell = k * NTHREADS + tid;
        v[k] = xb[2 * cell];
    }

    unsigned foodmask = 0;
    int nf = 0, no = 0;
    int fo = 1 << 30;   // first-opp candidate (min row-major idx)
#pragma unroll
    for (int k = 0; k < CELLS; k++) {
        const int cell = k * NTHREADS + tid;
        const bool food = (v[k].y == 1.0f);
        const bool opp  = (v[k].w == 1.0f);
        foodmask |= (unsigned)food << k;
        nf += food;
        no += opp;
        if (opp && cell < fo) fo = cell;
    }

    // Warp-level reductions
    nf = __reduce_add_sync(0xffffffffu, nf);
    no = __reduce_add_sync(0xffffffffu, no);
    fo = __reduce_min_sync(0xffffffffu, fo);

    __shared__ int   s_nf[8], s_no[8], s_fo[8];
    __shared__ float s_m1[8], s_m2[8];
    __shared__ int   s_i1[8];

    if (lid == 0) { s_nf[wid] = nf; s_no[wid] = no; s_fo[wid] = fo; }
    __syncthreads();

    // All threads redundantly fold the 8 warp partials (cheap; avoids broadcast)
    int tot_nf = 0, tot_no = 0, tfo = 1 << 30;
#pragma unroll
    for (int w = 0; w < 8; w++) {
        tot_nf += s_nf[w];
        tot_no += s_no[w];
        tfo = min(tfo, s_fo[w]);
    }
    if (tfo == (1 << 30)) tfo = 0;   // argmax over all-False == 0 (JAX semantics)
    const int orow = tfo >> 6;
    const int ocol = tfo & 63;

    // ---------------- Phase 2: two-smallest food distance (register pass) ---
    float m1 = FINF, m2 = FINF;
    int   i1 = 0;                    // argmin over all-INF row == 0
#pragma unroll
    for (int k = 0; k < CELLS; k++) {
        const int cell = k * NTHREADS + tid;
        if ((foodmask >> k) & 1u) {
            const int dr = (cell >> 6) - orow;
            const int dc = (cell & 63) - ocol;
            const float d = __fsqrt_rn((float)(dr * dr + dc * dc));
            if (d < m1) { m2 = m1; m1 = d; i1 = cell; }
            else        { m2 = fminf(m2, d); }
        }
    }

    // Warp butterfly reduce (all lanes converge to the same answer)
#pragma unroll
    for (int off = 16; off; off >>= 1) {
        const float m1b = __shfl_xor_sync(0xffffffffu, m1, off);
        const int   i1b = __shfl_xor_sync(0xffffffffu, i1, off);
        const float m2b = __shfl_xor_sync(0xffffffffu, m2, off);
        merge2min(m1, i1, m2, m1b, i1b, m2b);
    }
    if (lid == 0) { s_m1[wid] = m1; s_i1[wid] = i1; s_m2[wid] = m2; }
    __syncthreads();

    float M1 = s_m1[0], M2 = s_m2[0];
    int   I1 = s_i1[0];
#pragma unroll
    for (int w = 1; w < 8; w++) {
        merge2min(M1, I1, M2, s_m1[w], s_i1[w], s_m2[w]);
    }

    // ---------------- Branch logic (redundant per thread) -------------------
    const float os0 = __ldg(&opp_start[0]);
    const float os1 = __ldg(&opp_start[1]);
    const bool matches_start = ((float)orow == os0) && ((float)ocol == os1);
    const bool branchA = (tot_nf > 1) && (tot_no > 0) && !matches_start;
    const float diff = M2 - M1;   // only consumed when tot_nf > 1 (finite)
    const bool ambiguous    = (branchA && (diff <  0.1f)) || ((tot_nf > 1) && !branchA);
    const bool pick_nearest = (branchA && (diff >= 0.1f)) || (tot_nf == 1);

    // ---------------- Writeback ---------------------------------------------
    float* ob = out + (size_t)b * HW_;
#pragma unroll
    for (int k = 0; k < CELLS; k++) {
        const int cell = k * NTHREADS + tid;
        float hit;
        if (ambiguous)         hit = ((foodmask >> k) & 1u) ? 1.0f : 0.0f;
        else if (pick_nearest) hit = (cell == I1) ? 1.0f : 0.0f;
        else                   hit = 0.0f;
        ob[cell] = -10.0f + 20.0f * hit;
    }
}

extern "C" void kernel_launch(void* const* d_in, const int* in_sizes, int n_in,
                              void* d_out, int out_size) {
    const float* x         = (const float*)d_in[0];
    const float* opp_start = (const float*)d_in[1];
    float* out = (float*)d_out;

    const int B = in_sizes[0] / (HW_ * 8);   // 4096
    oracle_kernel<<<B, NTHREADS>>>(x, opp_start, out);
}